// round 3
// baseline (speedup 1.0000x reference)
#include <cuda_runtime.h>
#include <math.h>

#define NN 20000
#define EE 320000
#define CC 64
#define ZZ 10
#define LLAYERS 2
#define HH 64
#define NBES 8
#define TT 4096

// ---------------- scratch (device globals; no allocation allowed) ----------------
__device__ float  g_s[NN*CC];
__device__ float  g_v[NN*3*CC];
__device__ float4 g_up[NN*CC];                 // (s_up, vx, vy, vz)
__device__ float4 g_agg[NN*CC];                // (agg0, a1x, a1y, a1z)
__device__ float4 g_tab4[LLAYERS][TT*CC];      // (w00,w110,w011,w101)
__device__ float  g_tab1[LLAYERS][TT*CC];      // w111
// CSR by receiver
__device__ int    g_cnt[NN];
__device__ int    g_row[NN+1];
__device__ int    g_woff[NN];
__device__ int    g_se[EE];                    // sorted sender ids
__device__ float4 g_yu[EE];                    // sorted (y0,y1,y2,u)

__device__ __forceinline__ float silu_f(float x){ return x * (1.0f/(1.0f + __expf(-x))); }

// ---------------- CSR build ----------------
__global__ void k_cnt_zero()
{
    int i = blockIdx.x*blockDim.x + threadIdx.x;
    if (i < NN) g_cnt[i] = 0;
}

__global__ void k_hist(const int* __restrict__ eidx)
{
    int e = blockIdx.x*blockDim.x + threadIdx.x;
    if (e < EE) atomicAdd(&g_cnt[eidx[EE+e]], 1);
}

__global__ void k_scan()   // single block, 1024 threads
{
    __shared__ int partial[1024];
    int tid = threadIdx.x;
    const int PER = (NN + 1023)/1024;   // 20
    int base = tid*PER;
    int sum = 0;
    for (int i=0;i<PER;i++) if (base+i < NN) sum += g_cnt[base+i];
    partial[tid] = sum;
    __syncthreads();
    for (int off=1; off<1024; off<<=1){
        int v = (tid>=off) ? partial[tid-off] : 0;
        __syncthreads();
        partial[tid] += v;
        __syncthreads();
    }
    int run = (tid==0) ? 0 : partial[tid-1];
    if (tid == 1023) g_row[NN] = partial[1023];
    for (int i=0;i<PER;i++){
        if (base+i < NN){
            g_row[base+i] = run;
            g_woff[base+i] = run;
            run += g_cnt[base+i];
        }
    }
}

// scatter + fused geometry
__global__ void k_scatter(const float* __restrict__ pos, const float* __restrict__ shifts,
                          const int* __restrict__ eidx)
{
    int e = blockIdx.x*blockDim.x + threadIdx.x;
    if (e >= EE) return;
    int snd = eidx[e], rcv = eidx[EE + e];
    float vx = pos[rcv*3+0]-pos[snd*3+0]+shifts[e*3+0];
    float vy = pos[rcv*3+1]-pos[snd*3+1]+shifts[e*3+1];
    float vz = pos[rcv*3+2]-pos[snd*3+2]+shifts[e*3+2];
    float r = sqrtf(vx*vx+vy*vy+vz*vz);
    float inv = 1.0f/(r + 1e-9f);
    const float S3 = 1.7320508075688772f;
    int p = atomicAdd(&g_woff[rcv], 1);
    g_se[p] = snd;
    g_yu[p] = make_float4(S3*vx*inv, S3*vy*inv, S3*vz*inv, r*0.2f);
}

// ---------------- radial MLP table ----------------
__global__ void k_table(const float* __restrict__ RW1, const float* __restrict__ RW2,
                        const float* __restrict__ RW3)
{
    int i = blockIdx.x;              // table row
    int l = blockIdx.y;              // layer
    int t = threadIdx.x;             // 64 threads
    const float* W1 = RW1 + l*NBES*HH;
    const float* W2 = RW2 + l*HH*HH;
    const float* W3 = RW3 + l*HH*5*CC;
    __shared__ float feats[NBES], h1[HH], h2[HH];

    if (t < NBES) {
        float u = (float)i / (float)(TT-1);
        float r = 5.0f*u;
        float inv = 1.0f/(r + 1e-9f);
        float env = 0.0f;
        if (u < 1.0f) {
            float u2=u*u, u4=u2*u2, u6=u4*u2;
            env = 1.0f - 28.0f*u6 + 48.0f*u6*u - 21.0f*u6*u2;
        }
        float pref = 0.6324555320336759f * inv * env;
        const float PI = 3.14159265358979323846f;
        feats[t] = pref * sinf((float)(t+1) * PI * u);
    }
    __syncthreads();
    float a = 0.f;
    #pragma unroll
    for (int k=0;k<NBES;k++) a += feats[k]*W1[k*HH+t];
    h1[t] = silu_f(a);
    __syncthreads();
    a = 0.f;
    #pragma unroll 8
    for (int d=0;d<HH;d++) a += h1[d]*W2[d*HH+t];
    h2[t] = silu_f(a);
    __syncthreads();
    float o[5] = {};
    #pragma unroll 8
    for (int d=0;d<HH;d++){
        float h = h2[d];
        #pragma unroll
        for (int g=0;g<5;g++) o[g] += h*W3[d*320 + g*64 + t];
    }
    g_tab4[l][i*64 + t] = make_float4(o[0], o[1], o[2], o[3]);
    g_tab1[l][i*64 + t] = o[4];
}

// ---------------- embedding ----------------
__global__ void k_embed(const float* __restrict__ attrs, const float* __restrict__ Wemb)
{
    int idx = blockIdx.x*blockDim.x + threadIdx.x;
    if (idx >= NN*CC) return;
    int n = idx >> 6, c = idx & 63;
    float acc = 0.f;
    #pragma unroll
    for (int z=0; z<ZZ; z++) acc += __ldg(attrs + n*ZZ + z) * __ldg(Wemb + z*CC + c);
    g_s[idx] = acc;
    g_v[n*192 + c]       = 0.f;
    g_v[n*192 + 64 + c]  = 0.f;
    g_v[n*192 + 128 + c] = 0.f;
}

// ---------------- per-node channel-mix: s_up, v_up -> packed float4 ----------------
__global__ __launch_bounds__(256) void k_up(const float* __restrict__ Ws, const float* __restrict__ Wv)
{
    __shared__ float sWs[CC*CC], sWv[CC*CC];
    __shared__ float stg[8][256];
    int tid = threadIdx.x;
    for (int i=tid;i<CC*CC;i+=256){ sWs[i]=Ws[i]; sWv[i]=Wv[i]; }
    __syncthreads();
    int warp = tid>>5, lane = tid&31;
    for (int n = blockIdx.x*8 + warp; n < NN; n += gridDim.x*8) {
        stg[warp][lane]      = g_s[n*64+lane];
        stg[warp][lane+32]   = g_s[n*64+lane+32];
        #pragma unroll
        for (int j=lane; j<192; j+=32) stg[warp][64+j] = g_v[n*192+j];
        __syncwarp();
        float a0=0.f, a1=0.f, av[3][2]={};
        #pragma unroll 4
        for (int c=0;c<64;c++){
            float ws0=sWs[c*64+lane], ws1=sWs[c*64+lane+32];
            float wv0=sWv[c*64+lane], wv1=sWv[c*64+lane+32];
            float bs=stg[warp][c];
            a0 += bs*ws0; a1 += bs*ws1;
            #pragma unroll
            for (int i=0;i<3;i++){
                float bv = stg[warp][64+i*64+c];
                av[i][0]+=bv*wv0; av[i][1]+=bv*wv1;
            }
        }
        g_up[n*64+lane]    = make_float4(a0, av[0][0], av[1][0], av[2][0]);
        g_up[n*64+lane+32] = make_float4(a1, av[0][1], av[1][1], av[2][1]);
        __syncwarp();
    }
}

// ---------------- edge kernel: warp per receiver, register accumulation ----------------
__global__ __launch_bounds__(256) void k_edge(int layer)
{
    int warp = threadIdx.x>>5, lane = threadIdx.x&31;
    int n = blockIdx.x*8 + warp;
    if (n >= NN) return;
    int s0 = __ldg(&g_row[n]);
    int s1 = __ldg(&g_row[n+1]);

    const float4* tab4 = g_tab4[layer];
    const float*  tab1 = g_tab1[layer];
    const float IS3 = 0.5773502691896258f;
    const float IS2 = 0.7071067811865475f;

    float aA0=0.f,aA1=0.f,aA2=0.f,aA3=0.f;
    float aB0=0.f,aB1=0.f,aB2=0.f,aB3=0.f;

    for (int j=s0; j<s1; j++){
        int snd = __ldg(&g_se[j]);
        float4 yu = __ldg(&g_yu[j]);
        float u = yu.w;
        if (u >= 1.0f) continue;
        float t = u * (float)(TT-1);
        int i0 = (int)t; if (i0 > TT-2) i0 = TT-2;
        float f = t - (float)i0;
        const float4* rA = tab4 + i0*64;
        const float*  rB = tab1 + i0*64;

        // h = 0 : channel lane
        {
            int c = lane;
            float4 a4 = __ldg(rA + c);
            float4 b4 = __ldg(rA + 64 + c);
            float  a1 = __ldg(rB + c);
            float  b1 = __ldg(rB + 64 + c);
            float w0 = a4.x + f*(b4.x - a4.x);
            float w1 = a4.y + f*(b4.y - a4.y);
            float w2 = a4.z + f*(b4.z - a4.z);
            float w3 = a4.w + f*(b4.w - a4.w);
            float w4 = (a1 + f*(b1 - a1)) * IS2;
            float4 up = __ldg(&g_up[snd*64 + c]);
            float dv = up.y*yu.x + up.z*yu.y + up.w*yu.z;
            float cx = up.z*yu.z - up.w*yu.y;
            float cy = up.w*yu.x - up.y*yu.z;
            float cz = up.y*yu.y - up.z*yu.x;
            float sy = w2*up.x;
            aA0 += w0*up.x + w1*dv*IS3;
            aA1 += sy*yu.x + w3*up.y + w4*cx;
            aA2 += sy*yu.y + w3*up.z + w4*cy;
            aA3 += sy*yu.z + w3*up.w + w4*cz;
        }
        // h = 1 : channel lane+32
        {
            int c = lane + 32;
            float4 a4 = __ldg(rA + c);
            float4 b4 = __ldg(rA + 64 + c);
            float  a1 = __ldg(rB + c);
            float  b1 = __ldg(rB + 64 + c);
            float w0 = a4.x + f*(b4.x - a4.x);
            float w1 = a4.y + f*(b4.y - a4.y);
            float w2 = a4.z + f*(b4.z - a4.z);
            float w3 = a4.w + f*(b4.w - a4.w);
            float w4 = (a1 + f*(b1 - a1)) * IS2;
            float4 up = __ldg(&g_up[snd*64 + c]);
            float dv = up.y*yu.x + up.z*yu.y + up.w*yu.z;
            float cx = up.z*yu.z - up.w*yu.y;
            float cy = up.w*yu.x - up.y*yu.z;
            float cz = up.y*yu.y - up.z*yu.x;
            float sy = w2*up.x;
            aB0 += w0*up.x + w1*dv*IS3;
            aB1 += sy*yu.x + w3*up.y + w4*cx;
            aB2 += sy*yu.y + w3*up.z + w4*cy;
            aB3 += sy*yu.z + w3*up.w + w4*cz;
        }
    }
    const float IA = 1.0f/32.0f;
    g_agg[n*64 + lane]      = make_float4(aA0*IA, aA1*IA, aA2*IA, aA3*IA);
    g_agg[n*64 + lane + 32] = make_float4(aB0*IA, aB1*IA, aB2*IA, aB3*IA);
}

// ---------------- node update ----------------
#define NODE_SMEM_FLOATS (4*CC*CC + 8*768)

__global__ __launch_bounds__(256) void k_node(
    const float* __restrict__ attrs,
    const float* __restrict__ Wout_s, const float* __restrict__ Wout_v,
    const float* __restrict__ Wsc_s,  const float* __restrict__ Wsc_v,
    const float* __restrict__ P0,     const float* __restrict__ P1,
    const float* __restrict__ Wprod_s,const float* __restrict__ Wprod_v,
    float* __restrict__ outL)
{
    extern __shared__ float sm[];
    float* sWos = sm;
    float* sWov = sWos + 4096;
    float* sWps = sWov + 4096;
    float* sWpv = sWps + 4096;
    float* sStage = sWpv + 4096;
    int tid = threadIdx.x;
    for (int i=tid;i<4096;i+=blockDim.x){
        sWos[i]=Wout_s[i]; sWov[i]=Wout_v[i]; sWps[i]=Wprod_s[i]; sWpv[i]=Wprod_v[i];
    }
    __syncthreads();
    int warp = tid>>5, lane = tid&31;
    float* stg = sStage + warp*768;

    for (int n = blockIdx.x*8 + warp; n < NN; n += gridDim.x*8) {
        float av = (lane < ZZ) ? __ldg(attrs + n*ZZ + lane) : 0.f;
        unsigned msk = __ballot_sync(0xffffffffu, av > 0.5f);
        int z = __ffs(msk) - 1;

        float4 A = g_agg[n*64+lane];
        float4 B = g_agg[n*64+lane+32];
        stg[lane]        = A.x; stg[64+lane]     = A.y; stg[128+lane]    = A.z; stg[192+lane]    = A.w;
        stg[lane+32]     = B.x; stg[64+lane+32]  = B.y; stg[128+lane+32] = B.z; stg[192+lane+32] = B.w;
        stg[256+lane]    = g_s[n*64+lane];
        stg[256+lane+32] = g_s[n*64+lane+32];
        #pragma unroll
        for (int j=lane;j<192;j+=32) stg[320+j] = g_v[n*192+j];
        __syncwarp();

        const float* Wss = Wsc_s + (size_t)z*4096;
        const float* Wsv = Wsc_v + (size_t)z*4096;
        float ms0=0.f, ms1=0.f, scs0=0.f, scs1=0.f;
        float mv[3][2]={}, scv[3][2]={};
        #pragma unroll 4
        for (int c=0;c<64;c++){
            float a0 = stg[c];
            float sb = stg[256+c];
            float wos0=sWos[c*64+lane], wos1=sWos[c*64+lane+32];
            float wov0=sWov[c*64+lane], wov1=sWov[c*64+lane+32];
            float wss0=__ldg(Wss+c*64+lane), wss1=__ldg(Wss+c*64+lane+32);
            float wsv0=__ldg(Wsv+c*64+lane), wsv1=__ldg(Wsv+c*64+lane+32);
            ms0 += a0*wos0; ms1 += a0*wos1;
            scs0 += sb*wss0; scs1 += sb*wss1;
            #pragma unroll
            for (int i=0;i<3;i++){
                float a1 = stg[64+i*64+c];
                float vb = stg[320+i*64+c];
                mv[i][0]  += a1*wov0; mv[i][1]  += a1*wov1;
                scv[i][0] += vb*wsv0; scv[i][1] += vb*wsv1;
            }
        }

        const float* p0 = P0 + (size_t)z*CC*3;
        const float* q0 = P1 + (size_t)z*CC*2;
        float pa0=__ldg(p0+lane*3+0), pa1=__ldg(p0+lane*3+1), pa2=__ldg(p0+lane*3+2);
        float pb0=__ldg(p0+(lane+32)*3+0), pb1=__ldg(p0+(lane+32)*3+1), pb2=__ldg(p0+(lane+32)*3+2);
        float qa0=__ldg(q0+lane*2+0), qa1=__ldg(q0+lane*2+1);
        float qb0=__ldg(q0+(lane+32)*2+0), qb1=__ldg(q0+(lane+32)*2+1);

        float n2a = mv[0][0]*mv[0][0]+mv[1][0]*mv[1][0]+mv[2][0]*mv[2][0];
        float n2b = mv[0][1]*mv[0][1]+mv[1][1]*mv[1][1]+mv[2][1]*mv[2][1];
        stg[512+lane]    = pa0*ms0 + pa1*ms0*ms0 + pa2*n2a;
        stg[512+lane+32] = pb0*ms1 + pb1*ms1*ms1 + pb2*n2b;
        #pragma unroll
        for (int i=0;i<3;i++){
            stg[576+i*64+lane]    = qa0*mv[i][0] + qa1*ms0*mv[i][0];
            stg[576+i*64+lane+32] = qb0*mv[i][1] + qb1*ms1*mv[i][1];
        }
        __syncwarp();

        float sn0=scs0, sn1=scs1;
        float vn[3][2];
        #pragma unroll
        for (int i=0;i<3;i++){ vn[i][0]=scv[i][0]; vn[i][1]=scv[i][1]; }
        #pragma unroll 4
        for (int c=0;c<64;c++){
            float ps = stg[512+c];
            float wps0=sWps[c*64+lane], wps1=sWps[c*64+lane+32];
            float wpv0=sWpv[c*64+lane], wpv1=sWpv[c*64+lane+32];
            sn0 += ps*wps0; sn1 += ps*wps1;
            #pragma unroll
            for (int i=0;i<3;i++){
                float pv = stg[576+i*64+c];
                vn[i][0]+=pv*wpv0; vn[i][1]+=pv*wpv1;
            }
        }

        g_s[n*64+lane]=sn0; g_s[n*64+lane+32]=sn1;
        #pragma unroll
        for (int i=0;i<3;i++){
            g_v[n*192+i*64+lane]=vn[i][0];
            g_v[n*192+i*64+lane+32]=vn[i][1];
        }
        outL[n*128+lane]=sn0; outL[n*128+lane+32]=sn1;
        __syncwarp();
    }
}

// ---------------- launch ----------------
extern "C" void kernel_launch(void* const* d_in, const int* in_sizes, int n_in,
                              void* d_out, int out_size)
{
    const float* attrs   = (const float*)d_in[0];
    const float* pos     = (const float*)d_in[1];
    const float* shifts  = (const float*)d_in[2];
    const float* Wemb    = (const float*)d_in[3];
    const float* Wup_s   = (const float*)d_in[4];
    const float* Wup_v   = (const float*)d_in[5];
    const float* RW1     = (const float*)d_in[6];
    const float* RW2     = (const float*)d_in[7];
    const float* RW3     = (const float*)d_in[8];
    const float* Wout_s  = (const float*)d_in[9];
    const float* Wout_v  = (const float*)d_in[10];
    const float* Wsc_s   = (const float*)d_in[11];
    const float* Wsc_v   = (const float*)d_in[12];
    const float* P0      = (const float*)d_in[13];
    const float* P1      = (const float*)d_in[14];
    const float* Wprod_s = (const float*)d_in[15];
    const float* Wprod_v = (const float*)d_in[16];
    const int*   eidx    = (const int*)d_in[17];
    float* out = (float*)d_out;

    const int node_smem = NODE_SMEM_FLOATS * 4;
    cudaFuncSetAttribute(k_node, cudaFuncAttributeMaxDynamicSharedMemorySize, node_smem);

    // CSR build (fused geometry)
    k_cnt_zero<<<(NN+255)/256, 256>>>();
    k_hist<<<(EE+255)/256, 256>>>(eidx);
    k_scan<<<1, 1024>>>();
    k_scatter<<<(EE+255)/256, 256>>>(pos, shifts, eidx);

    k_embed<<<(NN*CC+255)/256, 256>>>(attrs, Wemb);
    k_table<<<dim3(TT, LLAYERS), 64>>>(RW1, RW2, RW3);

    for (int layer=0; layer<LLAYERS; layer++){
        k_up<<<592, 256>>>(Wup_s + layer*CC*CC, Wup_v + layer*CC*CC);
        k_edge<<<(NN+7)/8, 256>>>(layer);
        k_node<<<296, 256, node_smem>>>(
            attrs,
            Wout_s + layer*CC*CC, Wout_v + layer*CC*CC,
            Wsc_s + (size_t)layer*ZZ*CC*CC, Wsc_v + (size_t)layer*ZZ*CC*CC,
            P0 + (size_t)layer*ZZ*CC*3, P1 + (size_t)layer*ZZ*CC*2,
            Wprod_s + layer*CC*CC, Wprod_v + layer*CC*CC,
            out + layer*CC);
    }
}

// round 4
// speedup vs baseline: 1.4555x; 1.4555x over previous
#include <cuda_runtime.h>
#include <math.h>

#define NN 20000
#define EE 320000
#define CC 64
#define ZZ 10
#define LLAYERS 2
#define HH 64
#define NBES 8
#define TT 4096
#define NBINS (TT-1)

// ---------------- scratch (device globals; no allocation allowed) ----------------
__device__ float  g_s[NN*CC];
__device__ float  g_v[NN*3*CC];
__device__ float4 g_up[NN*CC];                 // (s_up, vx, vy, vz)
__device__ float4 g_agg[NN*CC];                // (agg0, a1x, a1y, a1z)
__device__ float4 g_tab4[LLAYERS][TT*CC];      // (w00, w110/√3, w011, w101) * 1/32
__device__ float  g_tab1[LLAYERS][TT*CC];      // w111/√2 * 1/32
// edge bins (by table row)
__device__ int    g_bcnt[NBINS];
__device__ int    g_brow[NBINS+1];
__device__ int    g_bwo[NBINS];
__device__ int2   g_esr[EE];                   // (sender, receiver)
__device__ float4 g_eyf[EE];                   // (y0, y1, y2, f)
// node z-sort
__device__ int    g_zcnt[ZZ];
__device__ int    g_zrow[ZZ+1];
__device__ int    g_zwo[ZZ];
__device__ int    g_nid[NN];

__device__ __forceinline__ float silu_f(float x){ return x * (1.0f/(1.0f + __expf(-x))); }

// ---------------- init counters ----------------
__global__ void k_init()
{
    int i = blockIdx.x*blockDim.x + threadIdx.x;
    if (i < NBINS) g_bcnt[i] = 0;
    if (i < ZZ)    g_zcnt[i] = 0;
}

// ---------------- edge histogram over table bins ----------------
__device__ __forceinline__ int edge_bin(const float* pos, const float* shifts,
                                        const int* eidx, int e, float* uo)
{
    int snd = eidx[e], rcv = eidx[EE + e];
    float vx = pos[rcv*3+0]-pos[snd*3+0]+shifts[e*3+0];
    float vy = pos[rcv*3+1]-pos[snd*3+1]+shifts[e*3+1];
    float vz = pos[rcv*3+2]-pos[snd*3+2]+shifts[e*3+2];
    float r = sqrtf(vx*vx+vy*vy+vz*vz);
    float u = r * 0.2f;
    *uo = u;
    if (u >= 1.0f) return -1;
    float t = u * (float)(TT-1);
    int i0 = (int)t;
    if (i0 > NBINS-1) i0 = NBINS-1;
    return i0;
}

__global__ void k_hist(const float* __restrict__ pos, const float* __restrict__ shifts,
                       const int* __restrict__ eidx)
{
    int e = blockIdx.x*blockDim.x + threadIdx.x;
    if (e >= EE) return;
    float u;
    int b = edge_bin(pos, shifts, eidx, e, &u);
    if (b >= 0) atomicAdd(&g_bcnt[b], 1);
}

__global__ void k_zhist(const float* __restrict__ attrs)
{
    int n = blockIdx.x*blockDim.x + threadIdx.x;
    if (n >= NN) return;
    int z = 0;
    #pragma unroll
    for (int j=0;j<ZZ;j++) if (__ldg(attrs + n*ZZ + j) > 0.5f) z = j;
    atomicAdd(&g_zcnt[z], 1);
}

__global__ void k_scan_bins()   // 1 block, 1024 threads
{
    __shared__ int partial[1024];
    int tid = threadIdx.x;
    const int PER = 4;          // 4*1024 = 4096 >= NBINS
    int base = tid*PER;
    int sum = 0;
    for (int i=0;i<PER;i++) if (base+i < NBINS) sum += g_bcnt[base+i];
    partial[tid] = sum;
    __syncthreads();
    for (int off=1; off<1024; off<<=1){
        int v = (tid>=off) ? partial[tid-off] : 0;
        __syncthreads();
        partial[tid] += v;
        __syncthreads();
    }
    int run = (tid==0) ? 0 : partial[tid-1];
    if (tid == 1023) g_brow[NBINS] = partial[1023];
    for (int i=0;i<PER;i++){
        if (base+i < NBINS){
            g_brow[base+i] = run;
            g_bwo[base+i]  = run;
            run += g_bcnt[base+i];
        }
    }
}

__global__ void k_zscan()
{
    if (threadIdx.x != 0 || blockIdx.x != 0) return;
    int run = 0;
    for (int z=0; z<ZZ; z++){
        g_zrow[z] = run; g_zwo[z] = run;
        run += g_zcnt[z];
    }
    g_zrow[ZZ] = run;
}

__global__ void k_scatter(const float* __restrict__ pos, const float* __restrict__ shifts,
                          const int* __restrict__ eidx)
{
    int e = blockIdx.x*blockDim.x + threadIdx.x;
    if (e >= EE) return;
    int snd = eidx[e], rcv = eidx[EE + e];
    float vx = pos[rcv*3+0]-pos[snd*3+0]+shifts[e*3+0];
    float vy = pos[rcv*3+1]-pos[snd*3+1]+shifts[e*3+1];
    float vz = pos[rcv*3+2]-pos[snd*3+2]+shifts[e*3+2];
    float r = sqrtf(vx*vx+vy*vy+vz*vz);
    float u = r * 0.2f;
    if (u >= 1.0f) return;
    float t = u * (float)(TT-1);
    int i0 = (int)t;
    if (i0 > NBINS-1) i0 = NBINS-1;
    float f = t - (float)i0;
    float inv = 1.0f/(r + 1e-9f);
    const float S3 = 1.7320508075688772f;
    int p = atomicAdd(&g_bwo[i0], 1);
    g_esr[p] = make_int2(snd, rcv);
    g_eyf[p] = make_float4(S3*vx*inv, S3*vy*inv, S3*vz*inv, f);
}

__global__ void k_zscatter(const float* __restrict__ attrs)
{
    int n = blockIdx.x*blockDim.x + threadIdx.x;
    if (n >= NN) return;
    int z = 0;
    #pragma unroll
    for (int j=0;j<ZZ;j++) if (__ldg(attrs + n*ZZ + j) > 0.5f) z = j;
    int p = atomicAdd(&g_zwo[z], 1);
    g_nid[p] = n;
}

// ---------------- radial MLP table (scales folded) ----------------
__global__ void k_table(const float* __restrict__ RW1, const float* __restrict__ RW2,
                        const float* __restrict__ RW3)
{
    int i = blockIdx.x;              // table row
    int l = blockIdx.y;              // layer
    int t = threadIdx.x;             // 64 threads
    const float* W1 = RW1 + l*NBES*HH;
    const float* W2 = RW2 + l*HH*HH;
    const float* W3 = RW3 + l*HH*5*CC;
    __shared__ float feats[NBES], h1[HH], h2[HH];

    if (t < NBES) {
        float u = (float)i / (float)(TT-1);
        float r = 5.0f*u;
        float inv = 1.0f/(r + 1e-9f);
        float env = 0.0f;
        if (u < 1.0f) {
            float u2=u*u, u4=u2*u2, u6=u4*u2;
            env = 1.0f - 28.0f*u6 + 48.0f*u6*u - 21.0f*u6*u2;
        }
        float pref = 0.6324555320336759f * inv * env;
        const float PI = 3.14159265358979323846f;
        feats[t] = pref * sinf((float)(t+1) * PI * u);
    }
    __syncthreads();
    float a = 0.f;
    #pragma unroll
    for (int k=0;k<NBES;k++) a += feats[k]*W1[k*HH+t];
    h1[t] = silu_f(a);
    __syncthreads();
    a = 0.f;
    #pragma unroll 8
    for (int d=0;d<HH;d++) a += h1[d]*W2[d*HH+t];
    h2[t] = silu_f(a);
    __syncthreads();
    float o[5] = {};
    #pragma unroll 8
    for (int d=0;d<HH;d++){
        float h = h2[d];
        #pragma unroll
        for (int g=0;g<5;g++) o[g] += h*W3[d*320 + g*64 + t];
    }
    const float IA  = 1.0f/32.0f;
    const float IS3 = 0.5773502691896258f;
    const float IS2 = 0.7071067811865475f;
    g_tab4[l][i*64 + t] = make_float4(o[0]*IA, o[1]*IA*IS3, o[2]*IA, o[3]*IA);
    g_tab1[l][i*64 + t] = o[4]*IA*IS2;
}

// ---------------- embedding ----------------
__global__ void k_embed(const float* __restrict__ attrs, const float* __restrict__ Wemb)
{
    int idx = blockIdx.x*blockDim.x + threadIdx.x;
    if (idx >= NN*CC) return;
    int n = idx >> 6, c = idx & 63;
    float acc = 0.f;
    #pragma unroll
    for (int z=0; z<ZZ; z++) acc += __ldg(attrs + n*ZZ + z) * __ldg(Wemb + z*CC + c);
    g_s[idx] = acc;
    g_v[n*192 + c]       = 0.f;
    g_v[n*192 + 64 + c]  = 0.f;
    g_v[n*192 + 128 + c] = 0.f;
}

// ---------------- s_up / v_up (2 nodes per warp) + agg zero ----------------
#define UP_SMEM_FLOATS (2*CC*CC + 8*512)

__global__ __launch_bounds__(256) void k_up(const float* __restrict__ Ws, const float* __restrict__ Wv)
{
    extern __shared__ float sm[];
    float* sWs = sm;
    float* sWv = sm + 4096;
    float* stg = sm + 8192;
    int tid = threadIdx.x;
    for (int i=tid;i<4096;i+=256){ sWs[i]=Ws[i]; sWv[i]=Wv[i]; }
    __syncthreads();
    int warp = tid>>5, lane = tid&31;
    int n0 = (blockIdx.x*8 + warp)*2;
    if (n0 >= NN) return;
    int nk = (n0+1 < NN) ? 2 : 1;
    float* st = stg + warp*512;
    float4 z4 = make_float4(0.f,0.f,0.f,0.f);
    for (int t=0;t<nk;t++){
        int n = n0 + t;
        st[t*256+lane]    = g_s[n*64+lane];
        st[t*256+lane+32] = g_s[n*64+lane+32];
        #pragma unroll
        for (int j=lane;j<192;j+=32) st[t*256+64+j] = g_v[n*192+j];
        g_agg[n*64+lane]    = z4;
        g_agg[n*64+lane+32] = z4;
    }
    __syncwarp();
    float a[2][2]={}, av[2][3][2]={};
    #pragma unroll 2
    for (int c=0;c<64;c++){
        float ws0=sWs[c*64+lane], ws1=sWs[c*64+lane+32];
        float wv0=sWv[c*64+lane], wv1=sWv[c*64+lane+32];
        #pragma unroll
        for (int t=0;t<2;t++){
            float bs = st[t*256+c];
            a[t][0]+=bs*ws0; a[t][1]+=bs*ws1;
            #pragma unroll
            for (int i=0;i<3;i++){
                float bv = st[t*256+64+i*64+c];
                av[t][i][0]+=bv*wv0; av[t][i][1]+=bv*wv1;
            }
        }
    }
    for (int t=0;t<nk;t++){
        int n = n0 + t;
        g_up[n*64+lane]    = make_float4(a[t][0], av[t][0][0], av[t][1][0], av[t][2][0]);
        g_up[n*64+lane+32] = make_float4(a[t][1], av[t][0][1], av[t][1][1], av[t][2][1]);
    }
}

// ---------------- edge kernel: block per u-bin, smem table, warp per edge ----------------
__global__ __launch_bounds__(256) void k_edge(int layer)
{
    __shared__ float4 sA4[CC], sD4[CC];
    __shared__ float  sA1[CC], sD1[CC];
    int bin = blockIdx.x;
    int s0 = __ldg(&g_brow[bin]);
    int s1 = __ldg(&g_brow[bin+1]);
    if (s0 == s1) return;
    int tid = threadIdx.x;
    if (tid < CC) {
        float4 a4 = g_tab4[layer][bin*CC + tid];
        float4 b4 = g_tab4[layer][(bin+1)*CC + tid];
        sA4[tid] = a4;
        sD4[tid] = make_float4(b4.x-a4.x, b4.y-a4.y, b4.z-a4.z, b4.w-a4.w);
        float a1 = g_tab1[layer][bin*CC + tid];
        float b1 = g_tab1[layer][(bin+1)*CC + tid];
        sA1[tid] = a1; sD1[tid] = b1 - a1;
    }
    __syncthreads();
    int warp = tid>>5, lane = tid&31;

    for (int j = s0 + warp; j < s1; j += 8) {
        int2   sr = __ldg(&g_esr[j]);
        float4 yf = __ldg(&g_eyf[j]);
        float f = yf.w;
        #pragma unroll
        for (int h=0; h<2; h++){
            int c = lane + h*32;
            float4 a4 = sA4[c], d4 = sD4[c];
            float w0 = fmaf(f, d4.x, a4.x);
            float w1 = fmaf(f, d4.y, a4.y);
            float w2 = fmaf(f, d4.z, a4.z);
            float w3 = fmaf(f, d4.w, a4.w);
            float w4 = fmaf(f, sD1[c], sA1[c]);
            float4 up = __ldg(&g_up[sr.x*64 + c]);   // (sj, v0, v1, v2)
            float dv = up.y*yf.x + up.z*yf.y + up.w*yf.z;
            float m0 = w0*up.x + w1*dv;
            float cx = up.z*yf.z - up.w*yf.y;
            float cy = up.w*yf.x - up.y*yf.z;
            float cz = up.y*yf.y - up.z*yf.x;
            float sy = w2*up.x;
            float m1x = sy*yf.x + w3*up.y + w4*cx;
            float m1y = sy*yf.y + w3*up.z + w4*cy;
            float m1z = sy*yf.z + w3*up.w + w4*cz;
            float* p = (float*)(g_agg + sr.y*64 + c);
            asm volatile("red.global.add.v4.f32 [%0], {%1,%2,%3,%4};"
                         :: "l"(p), "f"(m0), "f"(m1x), "f"(m1y), "f"(m1z) : "memory");
        }
    }
}

// ---------------- node update (z-sorted blocks) ----------------
#define NODE_SMEM_FLOATS (4*CC*CC + 8*768)
#define NODE_GX 64

__global__ __launch_bounds__(256) void k_node(
    const float* __restrict__ Wout_s, const float* __restrict__ Wout_v,
    const float* __restrict__ Wsc_sL, const float* __restrict__ Wsc_vL,   // layer base [Z][C][C]
    const float* __restrict__ P0L,    const float* __restrict__ P1L,      // layer base [Z][C][3],[Z][C][2]
    const float* __restrict__ Wprod_s,const float* __restrict__ Wprod_v,
    float* __restrict__ outL)
{
    int z  = blockIdx.y;
    int s0 = g_zrow[z];
    int s1 = g_zrow[z+1];
    if (s0 + (int)blockIdx.x*8 >= s1) return;

    extern __shared__ float sm[];
    float* sWos = sm;
    float* sWov = sWos + 4096;
    float* sWps = sWov + 4096;
    float* sWpv = sWps + 4096;
    float* sStage = sWpv + 4096;
    int tid = threadIdx.x;
    for (int i=tid;i<4096;i+=blockDim.x){
        sWos[i]=Wout_s[i]; sWov[i]=Wout_v[i]; sWps[i]=Wprod_s[i]; sWpv[i]=Wprod_v[i];
    }
    __syncthreads();
    int warp = tid>>5, lane = tid&31;
    float* stg = sStage + warp*768;

    const float* Wss = Wsc_sL + (size_t)z*4096;
    const float* Wsv = Wsc_vL + (size_t)z*4096;
    const float* p0  = P0L + (size_t)z*CC*3;
    const float* q0  = P1L + (size_t)z*CC*2;
    float pa0=__ldg(p0+lane*3+0), pa1=__ldg(p0+lane*3+1), pa2=__ldg(p0+lane*3+2);
    float pb0=__ldg(p0+(lane+32)*3+0), pb1=__ldg(p0+(lane+32)*3+1), pb2=__ldg(p0+(lane+32)*3+2);
    float qa0=__ldg(q0+lane*2+0), qa1=__ldg(q0+lane*2+1);
    float qb0=__ldg(q0+(lane+32)*2+0), qb1=__ldg(q0+(lane+32)*2+1);

    for (int idx = s0 + blockIdx.x*8 + warp; idx < s1; idx += NODE_GX*8) {
        int n = __ldg(&g_nid[idx]);

        float4 A = g_agg[n*64+lane];
        float4 B = g_agg[n*64+lane+32];
        stg[lane]        = A.x; stg[64+lane]     = A.y; stg[128+lane]    = A.z; stg[192+lane]    = A.w;
        stg[lane+32]     = B.x; stg[64+lane+32]  = B.y; stg[128+lane+32] = B.z; stg[192+lane+32] = B.w;
        stg[256+lane]    = g_s[n*64+lane];
        stg[256+lane+32] = g_s[n*64+lane+32];
        #pragma unroll
        for (int j=lane;j<192;j+=32) stg[320+j] = g_v[n*192+j];
        __syncwarp();

        float ms0=0.f, ms1=0.f, scs0=0.f, scs1=0.f;
        float mv[3][2]={}, scv[3][2]={};
        #pragma unroll 4
        for (int c=0;c<64;c++){
            float a0 = stg[c];
            float sb = stg[256+c];
            float wos0=sWos[c*64+lane], wos1=sWos[c*64+lane+32];
            float wov0=sWov[c*64+lane], wov1=sWov[c*64+lane+32];
            float wss0=__ldg(Wss+c*64+lane), wss1=__ldg(Wss+c*64+lane+32);
            float wsv0=__ldg(Wsv+c*64+lane), wsv1=__ldg(Wsv+c*64+lane+32);
            ms0 += a0*wos0; ms1 += a0*wos1;
            scs0 += sb*wss0; scs1 += sb*wss1;
            #pragma unroll
            for (int i=0;i<3;i++){
                float a1 = stg[64+i*64+c];
                float vb = stg[320+i*64+c];
                mv[i][0]  += a1*wov0; mv[i][1]  += a1*wov1;
                scv[i][0] += vb*wsv0; scv[i][1] += vb*wsv1;
            }
        }

        float n2a = mv[0][0]*mv[0][0]+mv[1][0]*mv[1][0]+mv[2][0]*mv[2][0];
        float n2b = mv[0][1]*mv[0][1]+mv[1][1]*mv[1][1]+mv[2][1]*mv[2][1];
        stg[512+lane]    = pa0*ms0 + pa1*ms0*ms0 + pa2*n2a;
        stg[512+lane+32] = pb0*ms1 + pb1*ms1*ms1 + pb2*n2b;
        #pragma unroll
        for (int i=0;i<3;i++){
            stg[576+i*64+lane]    = qa0*mv[i][0] + qa1*ms0*mv[i][0];
            stg[576+i*64+lane+32] = qb0*mv[i][1] + qb1*ms1*mv[i][1];
        }
        __syncwarp();

        float sn0=scs0, sn1=scs1;
        float vn[3][2];
        #pragma unroll
        for (int i=0;i<3;i++){ vn[i][0]=scv[i][0]; vn[i][1]=scv[i][1]; }
        #pragma unroll 4
        for (int c=0;c<64;c++){
            float ps = stg[512+c];
            float wps0=sWps[c*64+lane], wps1=sWps[c*64+lane+32];
            float wpv0=sWpv[c*64+lane], wpv1=sWpv[c*64+lane+32];
            sn0 += ps*wps0; sn1 += ps*wps1;
            #pragma unroll
            for (int i=0;i<3;i++){
                float pv = stg[576+i*64+c];
                vn[i][0]+=pv*wpv0; vn[i][1]+=pv*wpv1;
            }
        }

        g_s[n*64+lane]=sn0; g_s[n*64+lane+32]=sn1;
        #pragma unroll
        for (int i=0;i<3;i++){
            g_v[n*192+i*64+lane]=vn[i][0];
            g_v[n*192+i*64+lane+32]=vn[i][1];
        }
        outL[n*128+lane]=sn0; outL[n*128+lane+32]=sn1;
        __syncwarp();
    }
}

// ---------------- launch ----------------
extern "C" void kernel_launch(void* const* d_in, const int* in_sizes, int n_in,
                              void* d_out, int out_size)
{
    const float* attrs   = (const float*)d_in[0];
    const float* pos     = (const float*)d_in[1];
    const float* shifts  = (const float*)d_in[2];
    const float* Wemb    = (const float*)d_in[3];
    const float* Wup_s   = (const float*)d_in[4];
    const float* Wup_v   = (const float*)d_in[5];
    const float* RW1     = (const float*)d_in[6];
    const float* RW2     = (const float*)d_in[7];
    const float* RW3     = (const float*)d_in[8];
    const float* Wout_s  = (const float*)d_in[9];
    const float* Wout_v  = (const float*)d_in[10];
    const float* Wsc_s   = (const float*)d_in[11];
    const float* Wsc_v   = (const float*)d_in[12];
    const float* P0      = (const float*)d_in[13];
    const float* P1      = (const float*)d_in[14];
    const float* Wprod_s = (const float*)d_in[15];
    const float* Wprod_v = (const float*)d_in[16];
    const int*   eidx    = (const int*)d_in[17];
    float* out = (float*)d_out;

    const int up_smem   = UP_SMEM_FLOATS * 4;
    const int node_smem = NODE_SMEM_FLOATS * 4;
    cudaFuncSetAttribute(k_up,   cudaFuncAttributeMaxDynamicSharedMemorySize, up_smem);
    cudaFuncSetAttribute(k_node, cudaFuncAttributeMaxDynamicSharedMemorySize, node_smem);

    // binning + z-sort prolog
    k_init<<<(NBINS+255)/256, 256>>>();
    k_hist<<<(EE+255)/256, 256>>>(pos, shifts, eidx);
    k_zhist<<<(NN+255)/256, 256>>>(attrs);
    k_scan_bins<<<1, 1024>>>();
    k_zscan<<<1, 32>>>();
    k_scatter<<<(EE+255)/256, 256>>>(pos, shifts, eidx);
    k_zscatter<<<(NN+255)/256, 256>>>(attrs);

    k_embed<<<(NN*CC+255)/256, 256>>>(attrs, Wemb);
    k_table<<<dim3(TT, LLAYERS), 64>>>(RW1, RW2, RW3);

    for (int layer=0; layer<LLAYERS; layer++){
        k_up<<<(NN+15)/16, 256, up_smem>>>(Wup_s + layer*CC*CC, Wup_v + layer*CC*CC);
        k_edge<<<NBINS, 256>>>(layer);
        k_node<<<dim3(NODE_GX, ZZ), 256, node_smem>>>(
            Wout_s + layer*CC*CC, Wout_v + layer*CC*CC,
            Wsc_s + (size_t)layer*ZZ*CC*CC, Wsc_v + (size_t)layer*ZZ*CC*CC,
            P0 + (size_t)layer*ZZ*CC*3, P1 + (size_t)layer*ZZ*CC*2,
            Wprod_s + layer*CC*CC, Wprod_v + layer*CC*CC,
            out + layer*CC);
    }
}